// round 4
// baseline (speedup 1.0000x reference)
#include <cuda_runtime.h>
#include <math.h>

#define NPTS 3072
#define NOUT 16
#define TI 32          // i-rows per block
#define TJ 256         // j-cols per block (= blockDim.x)

// Single-pass dense kernel: streams the whole [3072,3072,16] output (zeros +
// sparse Gaussian values) with coalesced STG.128, coords tiled via smem/regs.
__global__ __launch_bounds__(256) void dense_edge_kernel(
    const float* __restrict__ coord,
    const float* __restrict__ sig,
    float* __restrict__ out)
{
    __shared__ float4 s_i[TI];          // xi, yi, zi, sqi
    __shared__ float  s_inv[NOUT];      // 1/(2*sigma_c^2), reference rounding
    __shared__ float  s_qden, s_lo, s_hi;

    const int tid    = threadIdx.x;
    const int j_base = blockIdx.x * TJ;
    const int i_base = blockIdx.y * TI;
    const int j      = j_base + tid;

    if (tid < NOUT) {
        float s = sig[tid];
        s_inv[tid] = __fdiv_rn(1.0f, __fmul_rn(__fmul_rn(2.0f, s), s));
    }
    if (tid == 0) {
        float sm = sig[NOUT - 1];
        float qd = __fmul_rn(__fmul_rn(2.0f, sm), sm);
        s_qden = qd;
        s_lo = 0.105300f * qd;   // conservative fast-keep bound
        s_hi = 0.105420f * qd;   // conservative fast-drop bound
    }
    if (tid < TI) {
        int ig = i_base + tid;
        float x = coord[3 * ig + 0];
        float y = coord[3 * ig + 1];
        float z = coord[3 * ig + 2];
        float sq = __fadd_rn(__fadd_rn(__fmul_rn(x, x), __fmul_rn(y, y)),
                             __fmul_rn(z, z));
        s_i[tid] = make_float4(x, y, z, sq);
    }

    // j-coords register-resident across the whole i-loop
    const float xj = coord[3 * j + 0];
    const float yj = coord[3 * j + 1];
    const float zj = coord[3 * j + 2];
    const float sqj = __fadd_rn(__fadd_rn(__fmul_rn(xj, xj), __fmul_rn(yj, yj)),
                                __fmul_rn(zj, zj));
    __syncthreads();

    const float lo = s_lo, hi = s_hi, qden = s_qden;
    float4* base = reinterpret_cast<float4*>(
        out + ((size_t)i_base * NPTS + j) * NOUT);
    const size_t row_stride_f4 = (size_t)NPTS * NOUT / 4;   // float4s per i-row

#pragma unroll 4
    for (int ii = 0; ii < TI; ii++) {
        const float4 I = s_i[ii];
        const float dot = __fmaf_rn(I.z, zj, __fmaf_rn(I.y, yj, __fmul_rn(I.x, xj)));
        float d2 = __fsub_rn(__fadd_rn(I.w, sqj), __fmul_rn(2.0f, dot));
        d2 = fmaxf(d2, 0.0f);

        bool keep;
        if (d2 <= lo) {
            keep = (d2 > 0.0f) && ((i_base + ii) != j);
        } else if (d2 >= hi) {
            keep = false;
        } else {
            // boundary band: reproduce reference predicate exactly
            const float q = __fdiv_rn(d2, qden);
            if (q <= 0.105340f)       keep = true;
            else if (q >= 0.105380f)  keep = false;
            else                      keep = ((float)exp(-(double)q) >= 0.9f);
            keep = keep && (d2 > 0.0f) && ((i_base + ii) != j);
        }

        float4 r0 = make_float4(0.f, 0.f, 0.f, 0.f);
        float4 r1 = r0, r2 = r0, r3 = r0;
        if (keep) {
            float v[NOUT];
#pragma unroll
            for (int c = 0; c < NOUT; c++)
                v[c] = __expf(-__fmul_rn(d2, s_inv[c]));
            r0 = make_float4(v[0],  v[1],  v[2],  v[3]);
            r1 = make_float4(v[4],  v[5],  v[6],  v[7]);
            r2 = make_float4(v[8],  v[9],  v[10], v[11]);
            r3 = make_float4(v[12], v[13], v[14], v[15]);
        }

        base[0] = r0;
        base[1] = r1;
        base[2] = r2;
        base[3] = r3;
        base += row_stride_f4;
    }
}

extern "C" void kernel_launch(void* const* d_in, const int* in_sizes, int n_in,
                              void* d_out, int out_size)
{
    const float* coord = (const float*)d_in[0];   // [3072, 3] fp32
    const float* sig   = (const float*)d_in[1];   // [16] fp32
    float* out = (float*)d_out;                   // [1, 3072, 3072, 16] fp32

    dim3 block(TJ);
    dim3 grid(NPTS / TJ, NPTS / TI);   // (12, 96)
    dense_edge_kernel<<<grid, block>>>(coord, sig, out);
}

// round 5
// speedup vs baseline: 1.4961x; 1.4961x over previous
#include <cuda_runtime.h>
#include <math.h>

#define NPTS 3072
#define NOUT 16
#define TI 32          // i-rows per block
#define TJ 256         // j-cols per block (= blockDim.x)

// Sparse fill: warp-ballot compaction, cooperative 16-lane-per-edge writes.
// Bulk zeros are produced by the cudaMemsetAsync node (HBM write roofline).
__global__ __launch_bounds__(256) void sparse_fill_kernel(
    const float* __restrict__ coord,
    const float* __restrict__ sig,
    float* __restrict__ out)
{
    __shared__ float4 s_i[TI];          // xi, yi, zi, sqi
    __shared__ float  s_inv[NOUT];      // 1/(2*sigma_c^2), reference rounding
    __shared__ float  s_qden, s_lo, s_hi;

    const int tid    = threadIdx.x;
    const int lane   = tid & 31;
    const int j_base = blockIdx.x * TJ;
    const int i_base = blockIdx.y * TI;
    const int j      = j_base + tid;
    const int jw     = j_base + (tid & ~31);   // warp's j origin

    if (tid < NOUT) {
        float s = sig[tid];
        s_inv[tid] = __fdiv_rn(1.0f, __fmul_rn(__fmul_rn(2.0f, s), s));
    }
    if (tid == 0) {
        float sm = sig[NOUT - 1];
        float qd = __fmul_rn(__fmul_rn(2.0f, sm), sm);
        s_qden = qd;
        s_lo = 0.105300f * qd;   // conservative fast-keep bound
        s_hi = 0.105420f * qd;   // conservative fast-drop bound
    }
    if (tid < TI) {
        int ig = i_base + tid;
        float x = coord[3 * ig + 0];
        float y = coord[3 * ig + 1];
        float z = coord[3 * ig + 2];
        float sq = __fadd_rn(__fadd_rn(__fmul_rn(x, x), __fmul_rn(y, y)),
                             __fmul_rn(z, z));
        s_i[tid] = make_float4(x, y, z, sq);
    }

    // j-coords register-resident across the whole i-loop
    const float xj = coord[3 * j + 0];
    const float yj = coord[3 * j + 1];
    const float zj = coord[3 * j + 2];
    const float sqj = __fadd_rn(__fadd_rn(__fmul_rn(xj, xj), __fmul_rn(yj, yj)),
                                __fmul_rn(zj, zj));
    __syncthreads();

    const float lo = s_lo, hi = s_hi, qden = s_qden;
    const int   c    = lane & (NOUT - 1);      // my output channel
    const float invc = s_inv[c];

    for (int ii = 0; ii < TI; ii++) {
        const float4 I = s_i[ii];
        const float dot = __fmaf_rn(I.z, zj, __fmaf_rn(I.y, yj, __fmul_rn(I.x, xj)));
        float d2 = __fsub_rn(__fadd_rn(I.w, sqj), __fmul_rn(2.0f, dot));
        d2 = fmaxf(d2, 0.0f);

        bool keep;
        if (d2 <= lo) {
            keep = (d2 > 0.0f) && ((i_base + ii) != j);
        } else if (d2 >= hi) {
            keep = false;
        } else {
            // boundary band: reproduce reference predicate exactly
            const float q = __fdiv_rn(d2, qden);
            if (q <= 0.105340f)       keep = true;
            else if (q >= 0.105380f)  keep = false;
            else                      keep = ((float)exp(-(double)q) >= 0.9f);
            keep = keep && (d2 > 0.0f) && ((i_base + ii) != j);
        }

        unsigned m = __ballot_sync(0xffffffffu, keep);
        if (m) {
            float* rowp = out + (size_t)(i_base + ii) * (NPTS * NOUT);
            do {
                const int e0 = __ffs(m) - 1;
                m &= m - 1u;
                const int e1 = m ? (__ffs(m) - 1) : -1;
                if (e1 >= 0) m &= m - 1u;

                const int  src   = (lane < 16) ? e0 : (e1 >= 0 ? e1 : e0);
                const bool valid = (lane < 16) || (e1 >= 0);
                const float d2v  = __shfl_sync(0xffffffffu, d2, src);
                const float v    = __expf(-__fmul_rn(d2v, invc));
                if (valid)
                    rowp[(size_t)(jw + src) * NOUT + c] = v;
            } while (m);
        }
    }
}

extern "C" void kernel_launch(void* const* d_in, const int* in_sizes, int n_in,
                              void* d_out, int out_size)
{
    const float* coord = (const float*)d_in[0];   // [3072, 3] fp32
    const float* sig   = (const float*)d_in[1];   // [16] fp32
    float* out = (float*)d_out;                   // [1, 3072, 3072, 16] fp32

    // Bulk zeros at the HBM write roofline (graph memset node).
    cudaMemsetAsync(d_out, 0, (size_t)NPTS * NPTS * NOUT * sizeof(float), 0);

    dim3 block(TJ);
    dim3 grid(NPTS / TJ, NPTS / TI);   // (12, 96)
    sparse_fill_kernel<<<grid, block>>>(coord, sig, out);
}